// round 12
// baseline (speedup 1.0000x reference)
#include <cuda_runtime.h>
#include <math_constants.h>

#define BATCH 8
#define HH 224
#define WW 224
#define OH 223
#define OW 223
#define NBLK 49          // 7x7 blocks per batch
#define NPIX (33 * 33)   // 1089 halo pixels
#define PI_F 3.14159265358979323846f

// Per-(batch,block) min/max partials — block-owned slots, written every launch.
__device__ float g_pmin[BATCH][NBLK];
__device__ float g_pmax[BATCH][NBLK];
// Monotonic ticket counter per batch (never reset; wrap-safe signed compare).
__device__ unsigned g_cnt[BATCH];

static __device__ __forceinline__ unsigned ldcg_u32(const unsigned* p) {
    unsigned v;
    asm volatile("ld.global.cg.u32 %0, [%1];" : "=r"(v) : "l"(p) : "memory");
    return v;
}
static __device__ __forceinline__ void stcg_f32(float* p, float v) {
    asm volatile("st.global.cg.f32 [%0], %1;" :: "l"(p), "f"(v) : "memory");
}

__global__ void __launch_bounds__(256)
quanv_fused(const float* __restrict__ x, const float* __restrict__ wts,
            float* __restrict__ out) {
    __shared__ float2 sTS[NPIX];        // {t = cos(a)cos(b), s = sin(a)}
    __shared__ float sred[16];          // 8 warp mins + 8 warp maxs
    __shared__ float s_rm[2][2];        // [min|max][warp]
    __shared__ float s_cw[4], s_sw[4];

    const int b   = blockIdx.z;
    const int blk = blockIdx.y * 7 + blockIdx.x;   // 0..48
    const int tid = threadIdx.x;
    const int r0  = blockIdx.y * 32;
    const int c0  = blockIdx.x * 32;

    if (tid < 4) {
        float w = wts[tid];
        s_cw[tid] = cosf(w);
        s_sw[tid] = sinf(w);
    }

    const float* xb = x + (size_t)b * 2 * HH * WW;
    const float* x0 = xb;
    const float* x1 = xb + HH * WW;

    // ---- Phase 1: coalesced min/max over this CTA's 1/49 slice (fast arrival) ----
    const float4* xv = (const float4*)xb;          // 25088 float4 per batch
    float lmin, lmax;
    {
        float4 v0 = xv[blk * 512 + tid];
        float4 v1 = xv[blk * 512 + 256 + tid];
        lmin = fminf(fminf(fminf(v0.x, v0.y), fminf(v0.z, v0.w)),
                     fminf(fminf(v1.x, v1.y), fminf(v1.z, v1.w)));
        lmax = fmaxf(fmaxf(fmaxf(v0.x, v0.y), fmaxf(v0.z, v0.w)),
                     fmaxf(fmaxf(v1.x, v1.y), fmaxf(v1.z, v1.w)));
    }
    #pragma unroll
    for (int off = 16; off > 0; off >>= 1) {
        lmin = fminf(lmin, __shfl_xor_sync(0xFFFFFFFFu, lmin, off));
        lmax = fmaxf(lmax, __shfl_xor_sync(0xFFFFFFFFu, lmax, off));
    }
    if ((tid & 31) == 0) { sred[tid >> 5] = lmin; sred[8 + (tid >> 5)] = lmax; }

    // ---- Prefetch halo pixels (complete during the barrier wait) ----
    float ra[5], rb[5];
    #pragma unroll
    for (int j = 0; j < 5; j++) {
        int i = tid + j * 256;
        if (i < NPIX) {
            int rr = i / 33, cc = i - rr * 33;
            int r = min(r0 + rr, HH - 1);
            int c = min(c0 + cc, WW - 1);
            ra[j] = __ldg(x0 + r * WW + c);
            rb[j] = __ldg(x1 + r * WW + c);
        }
    }
    __syncthreads();

    // ---- Publish partial + arrive (atomic ticket), wait via plain L2 loads ----
    if (tid == 0) {
        float m0 = sred[0], m1 = sred[8];
        #pragma unroll
        for (int i = 1; i < 8; i++) {
            m0 = fminf(m0, sred[i]);
            m1 = fmaxf(m1, sred[8 + i]);
        }
        __stcg(&g_pmin[b][blk], m0);
        __stcg(&g_pmax[b][blk], m1);
        __threadfence();                               // partials visible before arrive
        unsigned ticket = atomicAdd(&g_cnt[b], 1u);
        unsigned target = ticket - (ticket % NBLK) + NBLK;
        while ((int)(ldcg_u32(&g_cnt[b]) - target) < 0) { }
        __threadfence();                               // acquire
    }
    __syncthreads();

    // ---- Reduce the 49 partials (two warps, cross-warp combine) ----
    if (tid < 64) {
        float pm = CUDART_INF_F, px = -CUDART_INF_F;
        if (tid < NBLK) {
            pm = __ldcg(&g_pmin[b][tid]);
            px = __ldcg(&g_pmax[b][tid]);
        }
        #pragma unroll
        for (int off = 16; off > 0; off >>= 1) {
            pm = fminf(pm, __shfl_xor_sync(0xFFFFFFFFu, pm, off));
            px = fmaxf(px, __shfl_xor_sync(0xFFFFFFFFu, px, off));
        }
        if ((tid & 31) == 0) {
            s_rm[0][tid >> 5] = pm;
            s_rm[1][tid >> 5] = px;
        }
    }
    __syncthreads();

    const float fmn = fminf(s_rm[0][0], s_rm[0][1]);
    const float fmx = fmaxf(s_rm[1][0], s_rm[1][1]);
    const float scale = PI_F / (fmx - fmn + 1e-8f);
    const float nmn = -fmn * scale;                    // a = fma(v, scale, nmn)

    // ---- Transform registers -> packed smem ----
    #pragma unroll
    for (int j = 0; j < 5; j++) {
        int i = tid + j * 256;
        if (i < NPIX) {
            float a  = fmaf(ra[j], scale, nmn);
            float bb = fmaf(rb[j], scale, nmn);
            float sa, ca;
            __sincosf(a, &sa, &ca);
            sTS[i] = make_float2(ca * __cosf(bb), sa);
        }
    }
    __syncthreads();

    // ---- Output: z_i = cw_i*t - sw_i*s at 4 corners, parity products ----
    const float cw0 = s_cw[0], sw0 = s_sw[0];
    const float cw1 = s_cw[1], sw1 = s_sw[1];
    const float cw2 = s_cw[2], sw2 = s_sw[2];
    const float cw3 = s_cw[3], sw3 = s_sw[3];

    const int tx = tid & 31;
    const int ty = tid >> 5;
    const size_t plane = (size_t)OH * OW;
    float* ob = out + (size_t)b * 4 * plane;
    const bool interior = (blockIdx.x < 6) & (blockIdx.y < 6);

    #pragma unroll
    for (int k = 0; k < 4; k++) {
        int ly = ty * 4 + k;
        int oh = r0 + ly;
        int ow = c0 + tx;
        if (interior || (oh < OH && ow < OW)) {
            int p = ly * 33 + tx;
            float2 v0 = sTS[p];
            float2 v1 = sTS[p + 1];
            float2 v2 = sTS[p + 33];
            float2 v3 = sTS[p + 34];
            float z0 = fmaf(cw0, v0.x, -sw0 * v0.y);
            float z1 = fmaf(cw1, v1.x, -sw1 * v1.y);
            float z2 = fmaf(cw2, v2.x, -sw2 * v2.y);
            float z3 = fmaf(cw3, v3.x, -sw3 * v3.y);
            float z01 = z0 * z1;
            float z23 = z2 * z3;
            float* po = ob + (size_t)oh * OW + ow;
            stcg_f32(po,             z1 * z23);   // <Z0> = z1 z2 z3
            stcg_f32(po + plane,     z01);        // <Z1> = z0 z1
            stcg_f32(po + 2 * plane, z01 * z2);   // <Z2> = z0 z1 z2
            stcg_f32(po + 3 * plane, z01 * z23);  // <Z3> = z0 z1 z2 z3
        }
    }
}

extern "C" void kernel_launch(void* const* d_in, const int* in_sizes, int n_in,
                              void* d_out, int out_size) {
    const float* x   = (const float*)d_in[0];   // [8,2,224,224]
    const float* wts = (const float*)d_in[1];   // [1,4]
    float* out = (float*)d_out;                 // [8,4,223,223]

    dim3 grid(7, 7, BATCH);                     // 392 blocks, all co-resident
    quanv_fused<<<grid, 256>>>(x, wts, out);
}

// round 13
// speedup vs baseline: 1.0332x; 1.0332x over previous
#include <cuda_runtime.h>
#include <math_constants.h>

#define BATCH 8
#define HH 224
#define WW 224
#define OH 223
#define OW 223
#define NBLK 49          // 7x7 blocks per batch
#define NPIX (33 * 33)   // 1089 halo pixels
#define PI_F 3.14159265358979323846f

// Per-(batch,block) {min,max} partial, padded to 128B so each slot lands on a
// different L2 slice (gather is then parallel across slices, not one hot slice).
struct __align__(128) MMSlot { float mn; float mx; float pad[30]; };
__device__ MMSlot g_slot[BATCH][NBLK];
// Monotonic per-batch arrival counter (never reset; wrap-safe signed compare).
__device__ unsigned g_cnt[BATCH];

static __device__ __forceinline__ unsigned ldcg_u32(const unsigned* p) {
    unsigned v;
    asm volatile("ld.global.cg.u32 %0, [%1];" : "=r"(v) : "l"(p) : "memory");
    return v;
}
static __device__ __forceinline__ float2 ldcg_f2(const float* p) {
    float2 v;
    asm volatile("ld.global.cg.v2.f32 {%0,%1}, [%2];"
                 : "=f"(v.x), "=f"(v.y) : "l"(p) : "memory");
    return v;
}
static __device__ __forceinline__ void stcg_f2(float* p, float a, float b) {
    asm volatile("st.global.cg.v2.f32 [%0], {%1,%2};"
                 :: "l"(p), "f"(a), "f"(b) : "memory");
}
static __device__ __forceinline__ void redg_add(unsigned* p) {
    asm volatile("red.global.add.u32 [%0], 1;" :: "l"(p) : "memory");
}

__global__ void __launch_bounds__(256)
quanv_fused(const float* __restrict__ x, const float* __restrict__ wts,
            float* __restrict__ out) {
    __shared__ float2 sTS[NPIX];        // {t = cos(a)cos(b), s = sin(a)}
    __shared__ float sred[16];          // 8 warp mins + 8 warp maxs
    __shared__ float s_rm[2][2];        // [min|max][warp]
    __shared__ float s_cw[4], s_sw[4];

    const int b   = blockIdx.z;
    const int blk = blockIdx.y * 7 + blockIdx.x;   // 0..48
    const int tid = threadIdx.x;
    const int r0  = blockIdx.y * 32;
    const int c0c = blockIdx.x * 32;

    // Read the arrival counter BEFORE our own arrival: cnt is in
    // [49k, 49k+48] here, so base = c0 - c0%49 identifies this launch's
    // generation exactly (launches are stream-serialized).
    unsigned c0 = 0;
    if (tid == 0) c0 = ldcg_u32(&g_cnt[b]);

    if (tid < 4) {
        float w = wts[tid];
        s_cw[tid] = cosf(w);
        s_sw[tid] = sinf(w);
    }

    const float* xb = x + (size_t)b * 2 * HH * WW;
    const float* x0 = xb;
    const float* x1 = xb + HH * WW;

    // ---- Phase 1: coalesced min/max over this CTA's 1/49 slice ----
    const float4* xv = (const float4*)xb;          // 25088 float4 per batch
    float lmin, lmax;
    {
        float4 v0 = xv[blk * 512 + tid];
        float4 v1 = xv[blk * 512 + 256 + tid];
        lmin = fminf(fminf(fminf(v0.x, v0.y), fminf(v0.z, v0.w)),
                     fminf(fminf(v1.x, v1.y), fminf(v1.z, v1.w)));
        lmax = fmaxf(fmaxf(fmaxf(v0.x, v0.y), fmaxf(v0.z, v0.w)),
                     fmaxf(fmaxf(v1.x, v1.y), fmaxf(v1.z, v1.w)));
    }
    #pragma unroll
    for (int off = 16; off > 0; off >>= 1) {
        lmin = fminf(lmin, __shfl_xor_sync(0xFFFFFFFFu, lmin, off));
        lmax = fmaxf(lmax, __shfl_xor_sync(0xFFFFFFFFu, lmax, off));
    }
    if ((tid & 31) == 0) { sred[tid >> 5] = lmin; sred[8 + (tid >> 5)] = lmax; }

    // ---- Prefetch halo pixels (complete during the barrier wait) ----
    float ra[5], rb[5];
    #pragma unroll
    for (int j = 0; j < 5; j++) {
        int i = tid + j * 256;
        if (i < NPIX) {
            int rr = i / 33, cc = i - rr * 33;
            int r = min(r0 + rr, HH - 1);
            int c = min(c0c + cc, WW - 1);
            ra[j] = __ldg(x0 + r * WW + c);
            rb[j] = __ldg(x1 + r * WW + c);
        }
    }
    __syncthreads();

    // ---- Publish partial, fire-and-forget arrival, poll by plain L2 loads ----
    if (tid == 0) {
        float m0 = sred[0], m1 = sred[8];
        #pragma unroll
        for (int i = 1; i < 8; i++) {
            m0 = fminf(m0, sred[i]);
            m1 = fmaxf(m1, sred[8 + i]);
        }
        stcg_f2(&g_slot[b][blk].mn, m0, m1);
        __threadfence();                       // partial visible before arrival
        redg_add(&g_cnt[b]);                   // no-return arrival
        unsigned target = c0 - (c0 % NBLK) + NBLK;
        while ((int)(ldcg_u32(&g_cnt[b]) - target) < 0) { }
        __threadfence();                       // acquire
    }
    __syncthreads();

    // ---- Gather 49 partials (2 warps, one slot per lane, slices in parallel) ----
    if (tid < 64) {
        float pm = CUDART_INF_F, px = -CUDART_INF_F;
        if (tid < NBLK) {
            float2 v = ldcg_f2(&g_slot[b][tid].mn);
            pm = v.x; px = v.y;
        }
        #pragma unroll
        for (int off = 16; off > 0; off >>= 1) {
            pm = fminf(pm, __shfl_xor_sync(0xFFFFFFFFu, pm, off));
            px = fmaxf(px, __shfl_xor_sync(0xFFFFFFFFu, px, off));
        }
        if ((tid & 31) == 0) {
            s_rm[0][tid >> 5] = pm;
            s_rm[1][tid >> 5] = px;
        }
    }
    __syncthreads();

    const float fmn = fminf(s_rm[0][0], s_rm[0][1]);
    const float fmx = fmaxf(s_rm[1][0], s_rm[1][1]);
    const float scale = PI_F / (fmx - fmn + 1e-8f);
    const float nmn = -fmn * scale;            // a = fma(v, scale, nmn)

    // ---- Transform registers -> packed smem ----
    #pragma unroll
    for (int j = 0; j < 5; j++) {
        int i = tid + j * 256;
        if (i < NPIX) {
            float a  = fmaf(ra[j], scale, nmn);
            float bb = fmaf(rb[j], scale, nmn);
            float sa, ca;
            __sincosf(a, &sa, &ca);
            sTS[i] = make_float2(ca * __cosf(bb), sa);
        }
    }
    __syncthreads();

    // ---- Output: z_i = cw_i*t - sw_i*s at 4 corners, parity products ----
    const float cw0 = s_cw[0], sw0 = s_sw[0];
    const float cw1 = s_cw[1], sw1 = s_sw[1];
    const float cw2 = s_cw[2], sw2 = s_sw[2];
    const float cw3 = s_cw[3], sw3 = s_sw[3];

    const int tx = tid & 31;
    const int ty = tid >> 5;
    const size_t plane = (size_t)OH * OW;
    float* ob = out + (size_t)b * 4 * plane;

    #pragma unroll
    for (int k = 0; k < 4; k++) {
        int ly = ty * 4 + k;
        int oh = r0 + ly;
        int ow = c0c + tx;
        if (oh < OH && ow < OW) {
            int p = ly * 33 + tx;
            float2 v0 = sTS[p];
            float2 v1 = sTS[p + 1];
            float2 v2 = sTS[p + 33];
            float2 v3 = sTS[p + 34];
            float z0 = fmaf(cw0, v0.x, -sw0 * v0.y);
            float z1 = fmaf(cw1, v1.x, -sw1 * v1.y);
            float z2 = fmaf(cw2, v2.x, -sw2 * v2.y);
            float z3 = fmaf(cw3, v3.x, -sw3 * v3.y);
            float z01 = z0 * z1;
            float z23 = z2 * z3;
            size_t o = (size_t)oh * OW + ow;
            ob[0 * plane + o] = z1 * z23;   // <Z0> = z1 z2 z3
            ob[1 * plane + o] = z01;        // <Z1> = z0 z1
            ob[2 * plane + o] = z01 * z2;   // <Z2> = z0 z1 z2
            ob[3 * plane + o] = z01 * z23;  // <Z3> = z0 z1 z2 z3
        }
    }
}

extern "C" void kernel_launch(void* const* d_in, const int* in_sizes, int n_in,
                              void* d_out, int out_size) {
    const float* x   = (const float*)d_in[0];   // [8,2,224,224]
    const float* wts = (const float*)d_in[1];   // [1,4]
    float* out = (float*)d_out;                 // [8,4,223,223]

    dim3 grid(7, 7, BATCH);                     // 392 blocks, all co-resident
    quanv_fused<<<grid, 256>>>(x, wts, out);
}